// round 9
// baseline (speedup 1.0000x reference)
#include <cuda_runtime.h>
#include <cuda_bf16.h>
#include <cuda_fp16.h>
#include <cstdint>

#define Bq 4
#define Tq 2048
#define Cq 1024
#define Hq 16
#define Dh 64
#define MROWS (Bq*Tq)          // 8192
#define NHTD (Bq*Hq*Tq*Dh)     // 8,388,608

// ---------------------------------------------------------------------------
// Device-global scratch
// ---------------------------------------------------------------------------
__device__ __half g_q16[NHTD];           // post-rope, scaled log2e/8, f16 [b,h,t,d]
__device__ __half g_k16[NHTD];           // post-rope, f16 [b,h,t,d]
__device__ __half g_v16[NHTD];           // [b,h,t,d] f16

__device__ __half g_x16[MROWS*Cq];       // x in f16
__device__ __half g_wq16[3*Cq*Cq];       // w_qkv in f16
__device__ __half g_wo16[Cq*Cq];         // w_out in f16
__device__ __half g_o16[MROWS*Cq];       // attention output [b,t,h,d] f16

// ---------------------------------------------------------------------------
// helpers
// ---------------------------------------------------------------------------
__device__ __forceinline__ uint32_t s2u(const void* p){
    uint32_t a;
    asm("{ .reg .u64 t; cvta.to.shared.u64 t, %1; cvt.u32.u64 %0, t; }" : "=r"(a) : "l"(p));
    return a;
}
__device__ __forceinline__ void cp16(uint32_t dst, const void* src){
    asm volatile("cp.async.cg.shared.global [%0], [%1], 16;" :: "r"(dst), "l"(src));
}
__device__ __forceinline__ void ldmx4(uint32_t* r, uint32_t addr){
    asm volatile("ldmatrix.sync.aligned.m8n8.x4.shared.b16 {%0,%1,%2,%3}, [%4];"
                 : "=r"(r[0]), "=r"(r[1]), "=r"(r[2]), "=r"(r[3]) : "r"(addr));
}
__device__ __forceinline__ void ldmx4t(uint32_t* r, uint32_t addr){
    asm volatile("ldmatrix.sync.aligned.m8n8.x4.trans.shared.b16 {%0,%1,%2,%3}, [%4];"
                 : "=r"(r[0]), "=r"(r[1]), "=r"(r[2]), "=r"(r[3]) : "r"(addr));
}
__device__ __forceinline__ void mma_f16(float* c, const uint32_t* a, const uint32_t* b){
    asm volatile(
        "mma.sync.aligned.m16n8k16.row.col.f32.f16.f16.f32 "
        "{%0,%1,%2,%3}, {%4,%5,%6,%7}, {%8,%9}, {%0,%1,%2,%3};"
        : "+f"(c[0]), "+f"(c[1]), "+f"(c[2]), "+f"(c[3])
        : "r"(a[0]), "r"(a[1]), "r"(a[2]), "r"(a[3]), "r"(b[0]), "r"(b[1]));
}
__device__ __forceinline__ uint32_t cvt_f16x2(float lo, float hi){
    uint32_t r;
    asm("cvt.rn.f16x2.f32 %0, %1, %2;" : "=r"(r) : "f"(hi), "f"(lo));
    return r;
}
__device__ __forceinline__ uint32_t ex2_f16x2(uint32_t x){
    uint32_t r;
    asm("ex2.approx.f16x2 %0, %1;" : "=r"(r) : "r"(x));
    return r;
}
__device__ __forceinline__ float ex2f(float x){
    float r;
    asm("ex2.approx.ftz.f32 %0, %1;" : "=f"(r) : "f"(x));
    return r;
}

#define QSC 0.18033688011112042f   // log2(e)/8

// ---------------------------------------------------------------------------
// Fused fp32 -> fp16 convert of x, w_qkv, w_out in ONE launch.
// ---------------------------------------------------------------------------
#define NX4  (MROWS*Cq/4)        // 2,097,152
#define NWQ4 (3*Cq*Cq/4)         //   786,432
#define NWO4 (Cq*Cq/4)           //   262,144

__global__ void cvt_all_kernel(const float* __restrict__ x,
                               const float* __restrict__ wq,
                               const float* __restrict__ wo)
{
    int i = blockIdx.x * blockDim.x + threadIdx.x;
    const float* src; __half* dst; int off;
    if (i < NX4)              { src = x;  dst = g_x16;  off = i; }
    else if (i < NX4 + NWQ4)  { src = wq; dst = g_wq16; off = i - NX4; }
    else                      { src = wo; dst = g_wo16; off = i - NX4 - NWQ4; }
    float4 v = ((const float4*)src)[off];
    ((__half2*)dst)[2*off]   = __halves2half2(__float2half_rn(v.x), __float2half_rn(v.y));
    ((__half2*)dst)[2*off+1] = __halves2half2(__float2half_rn(v.z), __float2half_rn(v.w));
}

// ---------------------------------------------------------------------------
// Single-pass f16 HMMA GEMM, CTA tile 128x256, warp tile 64x64 (2x4 warps),
// K-chunk 64, 3-stage cp.async pipeline, 1 CTA/SM (no reg cap).
// EPI=0: C[m,Nfull] fp32.
// EPI=1: QKV epilogue — V f16 direct; Q/K staged in smem, RoPE fused, f16 out.
// ---------------------------------------------------------------------------
#define ROWB 128
#define OPA (128*ROWB)          // 16384 bytes (A tile)
#define OPBB (256*ROWB)         // 32768 bytes (B tile)
#define STB (OPA + OPBB)        // 49152 per stage
#define GEMM_SMEM (3*STB)       // 147456
#define EPAD 264                // padded f32 row for epilogue staging (256+8)

template<int EPI>
__global__ __launch_bounds__(256, 1)
void h16_gemm(const __half* __restrict__ A, const __half* __restrict__ B,
              float* __restrict__ C, int K, int Nfull,
              const float* __restrict__ cosT, const float* __restrict__ sinT)
{
    extern __shared__ __align__(1024) char smem[];
    const uint32_t sb = s2u(smem);

    const int tid  = threadIdx.x;
    const int lane = tid & 31;
    const int wid  = tid >> 5;
    const int wM   = wid >> 2;          // 0..1 (64 rows each)
    const int wN   = wid & 3;           // 0..3 (64 cols each)
    const int bm = blockIdx.y * 128;
    const int bn = blockIdx.x * 256;
    const int NC = K >> 6;              // 64-wide k-chunks

    float acc[4][8][4];
    #pragma unroll
    for (int i = 0; i < 4; i++)
        #pragma unroll
        for (int j = 0; j < 8; j++)
            #pragma unroll
            for (int q = 0; q < 4; q++) acc[i][j][q] = 0.0f;

    const int rA = ((lane >> 3) & 1) * 8 + (lane & 7);
    const int cA = (lane >> 4) & 1;
    const int rB = lane & 15;
    const int cB = lane >> 4;

    auto prefetch = [&](int c, int st){
        uint32_t base = sb + st * STB;
        int kc = c << 6;
        #pragma unroll
        for (int v = 0; v < 4; v++){                 // A: 128 rows
            int idx = tid + v * 256;
            int row = idx >> 3;
            int ch  = idx & 7;
            uint32_t sw = (uint32_t)(row * ROWB + ((ch ^ (row & 7)) << 4));
            cp16(base + sw, A + (size_t)(bm + row) * K + kc + ch * 8);
        }
        #pragma unroll
        for (int v = 0; v < 8; v++){                 // B: 256 rows
            int idx = tid + v * 256;
            int row = idx >> 3;
            int ch  = idx & 7;
            uint32_t sw = (uint32_t)(row * ROWB + ((ch ^ (row & 7)) << 4));
            cp16(base + OPA + sw, B + (size_t)(bn + row) * K + kc + ch * 8);
        }
        asm volatile("cp.async.commit_group;" ::: "memory");
    };

    prefetch(0, 0);
    prefetch(1, 1);
    asm volatile("cp.async.wait_group 1;" ::: "memory");
    __syncthreads();

    for (int c = 0; c < NC; c++){
        int st = c % 3;
        if (c + 2 < NC) prefetch(c + 2, (c + 2) % 3);

        uint32_t ab = sb + st * STB;
        uint32_t bb = ab + OPA;
        #pragma unroll
        for (int ks = 0; ks < 4; ks++){
            uint32_t a[4][4];
            #pragma unroll
            for (int i = 0; i < 4; i++){
                int arow = wM*64 + i*16 + rA;
                ldmx4(a[i], ab + arow*ROWB + (((ks*2 + cA) ^ (arow & 7)) << 4));
            }
            uint32_t br[4][4];
            #pragma unroll
            for (int j2 = 0; j2 < 4; j2++){
                int brow = wN*64 + j2*16 + rB;
                ldmx4(br[j2], bb + brow*ROWB + (((ks*2 + cB) ^ (brow & 7)) << 4));
            }
            uint32_t b[8][2];
            #pragma unroll
            for (int j2 = 0; j2 < 4; j2++){
                b[j2*2+0][0] = br[j2][0]; b[j2*2+0][1] = br[j2][2];
                b[j2*2+1][0] = br[j2][1]; b[j2*2+1][1] = br[j2][3];
            }
            #pragma unroll
            for (int i = 0; i < 4; i++)
                #pragma unroll
                for (int j = 0; j < 8; j++)
                    mma_f16(acc[i][j], a[i], b[j]);
        }

        if (c + 1 < NC){
            if (c + 2 < NC){ asm volatile("cp.async.wait_group 1;" ::: "memory"); }
            else           { asm volatile("cp.async.wait_group 0;" ::: "memory"); }
            __syncthreads();
        }
    }

    const int g  = lane >> 2;
    const int tg = lane & 3;
    const int part = bn >> 10;      // 256-col blocks never straddle a part

    if (EPI == 0 || part == 2){
        #pragma unroll
        for (int i = 0; i < 4; i++){
            #pragma unroll
            for (int j = 0; j < 8; j++){
                int col = bn + wN*64 + j*8 + tg*2;
                #pragma unroll
                for (int h2 = 0; h2 < 2; h2++){
                    int m = bm + wM*64 + i*16 + g + h2*8;
                    float2 val = make_float2(acc[i][j][h2*2], acc[i][j][h2*2+1]);
                    if (EPI == 0){
                        *(float2*)(C + (size_t)m * Nfull + col) = val;
                    } else {
                        int hh = (col >> 6) & (Hq - 1);
                        int d0 = col & (Dh - 1);
                        int b  = m >> 11;
                        int t  = m & (Tq - 1);
                        size_t idx = ((size_t)(b*Hq + hh) * Tq + t) * Dh + d0;
                        *(__half2*)(g_v16 + idx) = __halves2half2(
                            __float2half_rn(val.x), __float2half_rn(val.y));
                    }
                }
            }
        }
    } else {
        // Q or K tile: stage to smem (f32), apply RoPE, write f16
        __syncthreads();                      // mainloop smem reads complete
        float* sf = (float*)smem;
        #pragma unroll
        for (int i = 0; i < 4; i++){
            #pragma unroll
            for (int j = 0; j < 8; j++){
                int cl = wN*64 + j*8 + tg*2;
                #pragma unroll
                for (int h2 = 0; h2 < 2; h2++){
                    int ml = wM*64 + i*16 + g + h2*8;
                    *(float2*)&sf[ml*EPAD + cl] =
                        make_float2(acc[i][j][h2*2], acc[i][j][h2*2+1]);
                }
            }
        }
        __syncthreads();

        for (int k = 0; k < 64; k++){
            int p    = tid + k * 256;         // 0..16383
            int row  = p >> 7;                // 0..127
            int pd   = p & 127;
            int hloc = pd >> 5;               // head within tile (0..3)
            int d    = pd & 31;
            int m    = bm + row;
            int t    = m & (Tq - 1);
            int b    = m >> 11;
            float cv = cosT[t * Dh + d];      // cos[t][d] == cos[t][d+32]
            float sv = sinT[t * Dh + d];
            float u1 = sf[row * EPAD + hloc*64 + d];
            float u2 = sf[row * EPAD + hloc*64 + 32 + d];
            float r1 = u1 * cv - u2 * sv;
            float r2 = u2 * cv + u1 * sv;
            int colg = bn + hloc * 64;
            int h    = (colg >> 6) & (Hq - 1);
            size_t idx = ((size_t)(b*Hq + h) * Tq + t) * Dh + d;
            if (part == 0){
                g_q16[idx]      = __float2half_rn(r1 * QSC);
                g_q16[idx + 32] = __float2half_rn(r2 * QSC);
            } else {
                g_k16[idx]      = __float2half_rn(r1);
                g_k16[idx + 32] = __float2half_rn(r2);
            }
        }
    }
}

// ---------------------------------------------------------------------------
// Tensor-core flash attention (causal), all-f16 single-pass,
// single-barrier double-buffered mainloop. (unchanged — known-good)
// ---------------------------------------------------------------------------
#define FS_Q 0            // 128 x 128B
#define FS_K 16384        // buf b: +b*8192
#define FS_V 32768        // buf b: +b*8192
#define FLASH_SMEM 49152

__global__ __launch_bounds__(256)
void flash_tc()
{
    extern __shared__ __align__(1024) char fsm[];
    const uint32_t sb = s2u(fsm);
    const int tid  = threadIdx.x;
    const int lane = tid & 31;
    const int w    = tid >> 5;
    const int qt   = (int)(gridDim.x - 1 - blockIdx.x);
    const int bh   = blockIdx.y;
    const int b    = bh >> 4, h = bh & (Hq - 1);
    const int nkb  = 2 * qt + 2;

    {
        const __half* q16 = g_q16 + ((size_t)bh * Tq + (size_t)qt * 128) * Dh;
        #pragma unroll
        for (int v = 0; v < 4; v++){
            int idx = tid + v * 256;
            int row = idx >> 3;
            int c   = idx & 7;
            uint32_t sw = (uint32_t)(row * 128 + ((c ^ (row & 7)) << 4));
            cp16(sb + FS_Q + sw, q16 + (size_t)row * Dh + c * 8);
        }
    }

    auto prefetch = [&](int kt, int buf){
        size_t off = ((size_t)bh * Tq + (size_t)kt * 64) * Dh;
        const __half* k16 = g_k16 + off;
        const __half* v16 = g_v16 + off;
        #pragma unroll
        for (int v = 0; v < 2; v++){
            int idx = tid + v * 256;
            int row = idx >> 3;
            int c   = idx & 7;
            uint32_t sw = (uint32_t)(row * 128 + ((c ^ (row & 7)) << 4));
            cp16(sb + FS_K + buf*8192 + sw, k16 + (size_t)row * Dh + c * 8);
            cp16(sb + FS_V + buf*8192 + sw, v16 + (size_t)row * Dh + c * 8);
        }
        asm volatile("cp.async.commit_group;" ::: "memory");
    };

    prefetch(0, 0);
    asm volatile("cp.async.wait_group 0;" ::: "memory");
    __syncthreads();

    float sO[8][4];
    #pragma unroll
    for (int i = 0; i < 8; i++)
        #pragma unroll
        for (int q = 0; q < 4; q++) sO[i][q] = 0.0f;
    float lac[4] = {0.f, 0.f, 0.f, 0.f};
    float m0 = -1e30f, m1 = -1e30f;

    const int rA = ((lane >> 3) & 1) * 8 + (lane & 7);
    const int cA = (lane >> 4) & 1;
    const int rB = lane & 15;
    const int cB = lane >> 4;
    const int qrow = w * 16 + rA;
    const uint32_t ONE2 = 0x3C003C00u;
    const uint32_t ob[2] = {ONE2, ONE2};

    for (int kt = 0; kt < nkb; kt++){
        int buf = kt & 1;
        if (kt + 1 < nkb) prefetch(kt + 1, buf ^ 1);

        bool skip = (kt == 2*qt + 1) && (w < 4);
        if (!skip){
            float s[8][4];
            #pragma unroll
            for (int i = 0; i < 8; i++)
                #pragma unroll
                for (int q = 0; q < 4; q++) s[i][q] = 0.0f;

            uint32_t kb = sb + FS_K + buf*8192;
            #pragma unroll
            for (int ks = 0; ks < 4; ks++){
                uint32_t a[4];
                ldmx4(a, sb + FS_Q + qrow*128 + (((ks*2 + cA) ^ (qrow & 7)) << 4));
                #pragma unroll
                for (int j2 = 0; j2 < 4; j2++){
                    int krow = j2*16 + rB;
                    uint32_t br[4];
                    ldmx4(br, kb + krow*128 + (((ks*2 + cB) ^ (krow & 7)) << 4));
                    uint32_t b0[2] = {br[0], br[2]};
                    uint32_t b1[2] = {br[1], br[3]};
                    mma_f16(s[j2*2],     a, b0);
                    mma_f16(s[j2*2 + 1], a, b1);
                }
            }

            if (kt >= 2*qt){
                int co = (kt - 2*qt) * 64;
                int lr0 = w*16 + (lane >> 2);
                int lr1 = lr0 + 8;
                #pragma unroll
                for (int nt = 0; nt < 8; nt++){
                    int c0 = co + nt*8 + (lane & 3)*2;
                    if (c0     > lr0) s[nt][0] = -1e30f;
                    if (c0 + 1 > lr0) s[nt][1] = -1e30f;
                    if (c0     > lr1) s[nt][2] = -1e30f;
                    if (c0 + 1 > lr1) s[nt][3] = -1e30f;
                }
            }

            float mx0 = -1e30f, mx1 = -1e30f;
            #pragma unroll
            for (int nt = 0; nt < 8; nt++){
                mx0 = fmaxf(mx0, fmaxf(s[nt][0], s[nt][1]));
                mx1 = fmaxf(mx1, fmaxf(s[nt][2], s[nt][3]));
            }
            mx0 = fmaxf(mx0, __shfl_xor_sync(0xffffffffu, mx0, 1));
            mx0 = fmaxf(mx0, __shfl_xor_sync(0xffffffffu, mx0, 2));
            mx1 = fmaxf(mx1, __shfl_xor_sync(0xffffffffu, mx1, 1));
            mx1 = fmaxf(mx1, __shfl_xor_sync(0xffffffffu, mx1, 2));
            float mn0 = fmaxf(m0, mx0), mn1 = fmaxf(m1, mx1);
            float al0 = ex2f(m0 - mn0), al1 = ex2f(m1 - mn1);
            m0 = mn0; m1 = mn1;
            #pragma unroll
            for (int nt = 0; nt < 8; nt++){
                sO[nt][0] *= al0; sO[nt][1] *= al0;
                sO[nt][2] *= al1; sO[nt][3] *= al1;
            }
            lac[0] *= al0; lac[1] *= al0; lac[2] *= al1; lac[3] *= al1;

            uint32_t P[8][2];
            #pragma unroll
            for (int nt = 0; nt < 8; nt++){
                P[nt][0] = ex2_f16x2(cvt_f16x2(s[nt][0] - mn0, s[nt][1] - mn0));
                P[nt][1] = ex2_f16x2(cvt_f16x2(s[nt][2] - mn1, s[nt][3] - mn1));
            }

            #pragma unroll
            for (int ks = 0; ks < 4; ks++){
                uint32_t a[4] = {P[2*ks][0], P[2*ks][1], P[2*ks+1][0], P[2*ks+1][1]};
                mma_f16(lac, a, ob);
            }

            uint32_t vb = sb + FS_V + buf*8192;
            #pragma unroll
            for (int ks = 0; ks < 4; ks++){
                uint32_t a[4] = {P[2*ks][0], P[2*ks][1], P[2*ks+1][0], P[2*ks+1][1]};
                #pragma unroll
                for (int dt2 = 0; dt2 < 4; dt2++){
                    int vrow = ks*16 + (lane & 15);
                    int chnk = dt2*2 + (lane >> 4);
                    uint32_t br[4];
                    ldmx4t(br, vb + vrow*128 + ((chnk ^ (vrow & 7)) << 4));
                    uint32_t b0[2] = {br[0], br[1]};
                    uint32_t b1[2] = {br[2], br[3]};
                    mma_f16(sO[dt2*2],     a, b0);
                    mma_f16(sO[dt2*2 + 1], a, b1);
                }
            }
        }

        if (kt + 1 < nkb){
            asm volatile("cp.async.wait_group 0;" ::: "memory");
            __syncthreads();
        }
    }

    float inv0 = 1.0f / lac[0];
    float inv1 = 1.0f / lac[2];
    int tr0 = qt*128 + w*16 + (lane >> 2);
    int tr1 = tr0 + 8;
    #pragma unroll
    for (int dt = 0; dt < 8; dt++){
        int d = dt*8 + (lane & 3)*2;
        size_t i0 = ((size_t)(b * Tq + tr0) * Hq + h) * Dh + d;
        size_t i1 = ((size_t)(b * Tq + tr1) * Hq + h) * Dh + d;
        *(__half2*)(g_o16 + i0) = __halves2half2(
            __float2half_rn(sO[dt][0] * inv0), __float2half_rn(sO[dt][1] * inv0));
        *(__half2*)(g_o16 + i1) = __halves2half2(
            __float2half_rn(sO[dt][2] * inv1), __float2half_rn(sO[dt][3] * inv1));
    }
}

// ---------------------------------------------------------------------------
extern "C" void kernel_launch(void* const* d_in, const int* in_sizes, int n_in,
                              void* d_out, int out_size)
{
    (void)in_sizes; (void)n_in; (void)out_size;
    const float* x     = (const float*)d_in[0];
    const float* cosT  = (const float*)d_in[1];
    const float* sinT  = (const float*)d_in[2];
    const float* w_qkv = (const float*)d_in[3];
    const float* w_out = (const float*)d_in[4];
    float* out = (float*)d_out;

    void *p_x16, *p_wq16, *p_wo16, *p_o16;
    cudaGetSymbolAddress(&p_x16,  g_x16);
    cudaGetSymbolAddress(&p_wq16, g_wq16);
    cudaGetSymbolAddress(&p_wo16, g_wo16);
    cudaGetSymbolAddress(&p_o16,  g_o16);

    cudaFuncSetAttribute(flash_tc, cudaFuncAttributeMaxDynamicSharedMemorySize, FLASH_SMEM);
    cudaFuncSetAttribute(h16_gemm<0>, cudaFuncAttributeMaxDynamicSharedMemorySize, GEMM_SMEM);
    cudaFuncSetAttribute(h16_gemm<1>, cudaFuncAttributeMaxDynamicSharedMemorySize, GEMM_SMEM);

    // 1) fused fp32 -> fp16 converts (one launch)
    cvt_all_kernel<<<(NX4 + NWQ4 + NWO4) / 256, 256>>>(x, w_qkv, w_out);

    // 2) QKV projection with fused RoPE epilogue: Q,K f16 (rotated), V f16
    {
        dim3 grid(3*Cq / 256, MROWS / 128);   // (12, 64)
        h16_gemm<1><<<grid, 256, GEMM_SMEM>>>((const __half*)p_x16, (const __half*)p_wq16,
                                              nullptr, Cq, 3*Cq, cosT, sinT);
    }

    // 3) All-f16 tensor-core causal flash attention -> g_o16
    {
        dim3 grid(Tq / 128, Bq * Hq);
        flash_tc<<<grid, 256, FLASH_SMEM>>>();
    }

    // 4) Output projection
    {
        dim3 grid(Cq / 256, MROWS / 128);     // (4, 64)
        h16_gemm<0><<<grid, 256, GEMM_SMEM>>>((const __half*)p_o16, (const __half*)p_wo16,
                                              out, Cq, Cq, nullptr, nullptr);
    }
}

// round 10
// speedup vs baseline: 1.1123x; 1.1123x over previous
#include <cuda_runtime.h>
#include <cuda_bf16.h>
#include <cuda_fp16.h>
#include <cstdint>

#define Bq 4
#define Tq 2048
#define Cq 1024
#define Hq 16
#define Dh 64
#define MROWS (Bq*Tq)          // 8192
#define NHTD (Bq*Hq*Tq*Dh)     // 8,388,608

// ---------------------------------------------------------------------------
// Device-global scratch
// ---------------------------------------------------------------------------
__device__ __half g_q16[NHTD];           // post-rope, scaled log2e/8, f16 [b,h,t,d]
__device__ __half g_k16[NHTD];           // post-rope, f16 [b,h,t,d]
__device__ __half g_v16[NHTD];           // [b,h,t,d] f16

__device__ __half g_x16[MROWS*Cq];       // x in f16
__device__ __half g_wq16[3*Cq*Cq];       // w_qkv in f16
__device__ __half g_wo16[Cq*Cq];         // w_out in f16
__device__ __half g_o16[MROWS*Cq];       // attention output [b,t,h,d] f16

// ---------------------------------------------------------------------------
// helpers
// ---------------------------------------------------------------------------
__device__ __forceinline__ uint32_t s2u(const void* p){
    uint32_t a;
    asm("{ .reg .u64 t; cvta.to.shared.u64 t, %1; cvt.u32.u64 %0, t; }" : "=r"(a) : "l"(p));
    return a;
}
__device__ __forceinline__ void cp16(uint32_t dst, const void* src){
    asm volatile("cp.async.cg.shared.global [%0], [%1], 16;" :: "r"(dst), "l"(src));
}
__device__ __forceinline__ void ldmx4(uint32_t* r, uint32_t addr){
    asm volatile("ldmatrix.sync.aligned.m8n8.x4.shared.b16 {%0,%1,%2,%3}, [%4];"
                 : "=r"(r[0]), "=r"(r[1]), "=r"(r[2]), "=r"(r[3]) : "r"(addr));
}
__device__ __forceinline__ void ldmx4t(uint32_t* r, uint32_t addr){
    asm volatile("ldmatrix.sync.aligned.m8n8.x4.trans.shared.b16 {%0,%1,%2,%3}, [%4];"
                 : "=r"(r[0]), "=r"(r[1]), "=r"(r[2]), "=r"(r[3]) : "r"(addr));
}
__device__ __forceinline__ void mma_f16(float* c, const uint32_t* a, const uint32_t* b){
    asm volatile(
        "mma.sync.aligned.m16n8k16.row.col.f32.f16.f16.f32 "
        "{%0,%1,%2,%3}, {%4,%5,%6,%7}, {%8,%9}, {%0,%1,%2,%3};"
        : "+f"(c[0]), "+f"(c[1]), "+f"(c[2]), "+f"(c[3])
        : "r"(a[0]), "r"(a[1]), "r"(a[2]), "r"(a[3]), "r"(b[0]), "r"(b[1]));
}
__device__ __forceinline__ uint32_t cvt_f16x2(float lo, float hi){
    uint32_t r;
    asm("cvt.rn.f16x2.f32 %0, %1, %2;" : "=r"(r) : "f"(hi), "f"(lo));
    return r;
}
__device__ __forceinline__ uint32_t ex2_f16x2(uint32_t x){
    uint32_t r;
    asm("ex2.approx.f16x2 %0, %1;" : "=r"(r) : "r"(x));
    return r;
}
__device__ __forceinline__ float ex2f(float x){
    float r;
    asm("ex2.approx.ftz.f32 %0, %1;" : "=f"(r) : "f"(x));
    return r;
}

#define QSC 0.18033688011112042f   // log2(e)/8

// ---------------------------------------------------------------------------
// Fused fp32 -> fp16 convert of x, w_qkv, w_out in ONE launch.
// ---------------------------------------------------------------------------
#define NX4  (MROWS*Cq/4)        // 2,097,152
#define NWQ4 (3*Cq*Cq/4)         //   786,432
#define NWO4 (Cq*Cq/4)           //   262,144

__global__ void cvt_all_kernel(const float* __restrict__ x,
                               const float* __restrict__ wq,
                               const float* __restrict__ wo)
{
    int i = blockIdx.x * blockDim.x + threadIdx.x;
    const float* src; __half* dst; int off;
    if (i < NX4)              { src = x;  dst = g_x16;  off = i; }
    else if (i < NX4 + NWQ4)  { src = wq; dst = g_wq16; off = i - NX4; }
    else                      { src = wo; dst = g_wo16; off = i - NX4 - NWQ4; }
    float4 v = ((const float4*)src)[off];
    ((__half2*)dst)[2*off]   = __halves2half2(__float2half_rn(v.x), __float2half_rn(v.y));
    ((__half2*)dst)[2*off+1] = __halves2half2(__float2half_rn(v.z), __float2half_rn(v.w));
}

// ---------------------------------------------------------------------------
// Single-pass f16 HMMA GEMM (round-8 known-good shape):
// CTA 128x128, warp tile 64x32 (2x4 warps), K-chunk 64, 3-stage pipeline,
// 2 CTAs/SM. EPI=0: C fp32. EPI=1: V f16 direct; Q/K RoPE-fused f16 out.
// ---------------------------------------------------------------------------
#define ROWB 128
#define OPB (128*ROWB)          // 16384 bytes per operand tile
#define STB (2*OPB)             // 32768 per stage (A+B)
#define GEMM_SMEM (3*STB)       // 98304
#define EPAD 132                // padded f32 row for epilogue staging

template<int EPI>
__global__ __launch_bounds__(256, 2)
void h16_gemm(const __half* __restrict__ A, const __half* __restrict__ B,
              float* __restrict__ C, int K, int Nfull,
              const float* __restrict__ cosT, const float* __restrict__ sinT)
{
    extern __shared__ __align__(1024) char smem[];
    const uint32_t sb = s2u(smem);

    const int tid  = threadIdx.x;
    const int lane = tid & 31;
    const int wid  = tid >> 5;
    const int wM   = wid >> 2;
    const int wN   = wid & 3;
    const int bm = blockIdx.y * 128;
    const int bn = blockIdx.x * 128;
    const int NC = K >> 6;          // 64-wide k-chunks

    float acc[4][4][4];
    #pragma unroll
    for (int i = 0; i < 4; i++)
        #pragma unroll
        for (int j = 0; j < 4; j++)
            #pragma unroll
            for (int q = 0; q < 4; q++) acc[i][j][q] = 0.0f;

    const int rA = ((lane >> 3) & 1) * 8 + (lane & 7);
    const int cA = (lane >> 4) & 1;
    const int rB = lane & 15;
    const int cB = lane >> 4;

    auto prefetch = [&](int c, int st){
        uint32_t base = sb + st * STB;
        int kc = c << 6;
        #pragma unroll
        for (int v = 0; v < 4; v++){
            int idx = tid + v * 256;        // 0..1023
            int row = idx >> 3;             // 0..127
            int ch  = idx & 7;
            uint32_t sw = (uint32_t)(row * ROWB + ((ch ^ (row & 7)) << 4));
            cp16(base + sw,       A + (size_t)(bm + row) * K + kc + ch * 8);
            cp16(base + OPB + sw, B + (size_t)(bn + row) * K + kc + ch * 8);
        }
        asm volatile("cp.async.commit_group;" ::: "memory");
    };

    prefetch(0, 0);
    prefetch(1, 1);
    asm volatile("cp.async.wait_group 1;" ::: "memory");   // stage 0 ready
    __syncthreads();

    for (int c = 0; c < NC; c++){
        int st = c % 3;
        if (c + 2 < NC) prefetch(c + 2, (c + 2) % 3);      // overlaps compute(c)

        uint32_t ab = sb + st * STB;
        uint32_t bb = ab + OPB;
        #pragma unroll
        for (int ks = 0; ks < 4; ks++){
            uint32_t a[4][4];
            #pragma unroll
            for (int i = 0; i < 4; i++){
                int arow = wM*64 + i*16 + rA;
                ldmx4(a[i], ab + arow*ROWB + (((ks*2 + cA) ^ (arow & 7)) << 4));
            }
            uint32_t br[2][4];
            #pragma unroll
            for (int j2 = 0; j2 < 2; j2++){
                int brow = wN*32 + j2*16 + rB;
                ldmx4(br[j2], bb + brow*ROWB + (((ks*2 + cB) ^ (brow & 7)) << 4));
            }
            uint32_t b[4][2];
            #pragma unroll
            for (int j2 = 0; j2 < 2; j2++){
                b[j2*2+0][0] = br[j2][0]; b[j2*2+0][1] = br[j2][2];
                b[j2*2+1][0] = br[j2][1]; b[j2*2+1][1] = br[j2][3];
            }
            #pragma unroll
            for (int i = 0; i < 4; i++)
                #pragma unroll
                for (int j = 0; j < 4; j++)
                    mma_f16(acc[i][j], a[i], b[j]);
        }

        if (c + 1 < NC){
            if (c + 2 < NC){ asm volatile("cp.async.wait_group 1;" ::: "memory"); }
            else           { asm volatile("cp.async.wait_group 0;" ::: "memory"); }
            __syncthreads();
        }
    }

    const int g  = lane >> 2;
    const int tg = lane & 3;
    const int part = bn >> 10;

    if (EPI == 0 || part == 2){
        #pragma unroll
        for (int i = 0; i < 4; i++){
            #pragma unroll
            for (int j = 0; j < 4; j++){
                int col = bn + wN*32 + j*8 + tg*2;
                #pragma unroll
                for (int h2 = 0; h2 < 2; h2++){
                    int m = bm + wM*64 + i*16 + g + h2*8;
                    float2 val = make_float2(acc[i][j][h2*2], acc[i][j][h2*2+1]);
                    if (EPI == 0){
                        *(float2*)(C + (size_t)m * Nfull + col) = val;
                    } else {
                        int hh = (col >> 6) & (Hq - 1);
                        int d0 = col & (Dh - 1);
                        int b  = m >> 11;
                        int t  = m & (Tq - 1);
                        size_t idx = ((size_t)(b*Hq + hh) * Tq + t) * Dh + d0;
                        *(__half2*)(g_v16 + idx) = __halves2half2(
                            __float2half_rn(val.x), __float2half_rn(val.y));
                    }
                }
            }
        }
    } else {
        // Q or K tile: stage to smem, apply RoPE, write f16
        __syncthreads();                      // mainloop smem reads complete
        float* sf = (float*)smem;
        #pragma unroll
        for (int i = 0; i < 4; i++){
            #pragma unroll
            for (int j = 0; j < 4; j++){
                int cl = wN*32 + j*8 + tg*2;
                #pragma unroll
                for (int h2 = 0; h2 < 2; h2++){
                    int ml = wM*64 + i*16 + g + h2*8;
                    *(float2*)&sf[ml*EPAD + cl] =
                        make_float2(acc[i][j][h2*2], acc[i][j][h2*2+1]);
                }
            }
        }
        __syncthreads();

        for (int k = 0; k < 32; k++){
            int p    = tid + k * 256;         // 0..8191
            int row  = p >> 6;                // 0..127
            int pd   = p & 63;
            int hloc = pd >> 5;               // head within tile (0/1)
            int d    = pd & 31;
            int m    = bm + row;
            int t    = m & (Tq - 1);
            int b    = m >> 11;
            float cv = cosT[t * Dh + d];      // cos[t][d] == cos[t][d+32]
            float sv = sinT[t * Dh + d];
            float u1 = sf[row * EPAD + hloc*64 + d];
            float u2 = sf[row * EPAD + hloc*64 + 32 + d];
            float r1 = u1 * cv - u2 * sv;
            float r2 = u2 * cv + u1 * sv;
            int colg = bn + hloc * 64;
            int h    = (colg >> 6) & (Hq - 1);
            size_t idx = ((size_t)(b*Hq + h) * Tq + t) * Dh + d;
            if (part == 0){
                g_q16[idx]      = __float2half_rn(r1 * QSC);
                g_q16[idx + 32] = __float2half_rn(r2 * QSC);
            } else {
                g_k16[idx]      = __float2half_rn(r1);
                g_k16[idx + 32] = __float2half_rn(r2);
            }
        }
    }
}

// ---------------------------------------------------------------------------
// Tensor-core flash attention (causal), all-f16 single-pass,
// single-barrier double-buffered mainloop. Now 2 CTAs/SM (96KB smem total).
// ---------------------------------------------------------------------------
#define FS_Q 0            // 128 x 128B
#define FS_K 16384        // buf b: +b*8192
#define FS_V 32768        // buf b: +b*8192
#define FLASH_SMEM 49152

__global__ __launch_bounds__(256, 2)
void flash_tc()
{
    extern __shared__ __align__(1024) char fsm[];
    const uint32_t sb = s2u(fsm);
    const int tid  = threadIdx.x;
    const int lane = tid & 31;
    const int w    = tid >> 5;
    const int qt   = (int)(gridDim.x - 1 - blockIdx.x);
    const int bh   = blockIdx.y;
    const int b    = bh >> 4, h = bh & (Hq - 1);
    const int nkb  = 2 * qt + 2;

    {
        const __half* q16 = g_q16 + ((size_t)bh * Tq + (size_t)qt * 128) * Dh;
        #pragma unroll
        for (int v = 0; v < 4; v++){
            int idx = tid + v * 256;
            int row = idx >> 3;
            int c   = idx & 7;
            uint32_t sw = (uint32_t)(row * 128 + ((c ^ (row & 7)) << 4));
            cp16(sb + FS_Q + sw, q16 + (size_t)row * Dh + c * 8);
        }
    }

    auto prefetch = [&](int kt, int buf){
        size_t off = ((size_t)bh * Tq + (size_t)kt * 64) * Dh;
        const __half* k16 = g_k16 + off;
        const __half* v16 = g_v16 + off;
        #pragma unroll
        for (int v = 0; v < 2; v++){
            int idx = tid + v * 256;
            int row = idx >> 3;
            int c   = idx & 7;
            uint32_t sw = (uint32_t)(row * 128 + ((c ^ (row & 7)) << 4));
            cp16(sb + FS_K + buf*8192 + sw, k16 + (size_t)row * Dh + c * 8);
            cp16(sb + FS_V + buf*8192 + sw, v16 + (size_t)row * Dh + c * 8);
        }
        asm volatile("cp.async.commit_group;" ::: "memory");
    };

    prefetch(0, 0);
    asm volatile("cp.async.wait_group 0;" ::: "memory");
    __syncthreads();

    float sO[8][4];
    #pragma unroll
    for (int i = 0; i < 8; i++)
        #pragma unroll
        for (int q = 0; q < 4; q++) sO[i][q] = 0.0f;
    float lac[4] = {0.f, 0.f, 0.f, 0.f};
    float m0 = -1e30f, m1 = -1e30f;

    const int rA = ((lane >> 3) & 1) * 8 + (lane & 7);
    const int cA = (lane >> 4) & 1;
    const int rB = lane & 15;
    const int cB = lane >> 4;
    const int qrow = w * 16 + rA;
    const uint32_t ONE2 = 0x3C003C00u;
    const uint32_t ob[2] = {ONE2, ONE2};

    for (int kt = 0; kt < nkb; kt++){
        int buf = kt & 1;
        if (kt + 1 < nkb) prefetch(kt + 1, buf ^ 1);

        bool skip = (kt == 2*qt + 1) && (w < 4);
        if (!skip){
            float s[8][4];
            #pragma unroll
            for (int i = 0; i < 8; i++)
                #pragma unroll
                for (int q = 0; q < 4; q++) s[i][q] = 0.0f;

            uint32_t kb = sb + FS_K + buf*8192;
            #pragma unroll
            for (int ks = 0; ks < 4; ks++){
                uint32_t a[4];
                ldmx4(a, sb + FS_Q + qrow*128 + (((ks*2 + cA) ^ (qrow & 7)) << 4));
                #pragma unroll
                for (int j2 = 0; j2 < 4; j2++){
                    int krow = j2*16 + rB;
                    uint32_t br[4];
                    ldmx4(br, kb + krow*128 + (((ks*2 + cB) ^ (krow & 7)) << 4));
                    uint32_t b0[2] = {br[0], br[2]};
                    uint32_t b1[2] = {br[1], br[3]};
                    mma_f16(s[j2*2],     a, b0);
                    mma_f16(s[j2*2 + 1], a, b1);
                }
            }

            if (kt >= 2*qt){
                int co = (kt - 2*qt) * 64;
                int lr0 = w*16 + (lane >> 2);
                int lr1 = lr0 + 8;
                #pragma unroll
                for (int nt = 0; nt < 8; nt++){
                    int c0 = co + nt*8 + (lane & 3)*2;
                    if (c0     > lr0) s[nt][0] = -1e30f;
                    if (c0 + 1 > lr0) s[nt][1] = -1e30f;
                    if (c0     > lr1) s[nt][2] = -1e30f;
                    if (c0 + 1 > lr1) s[nt][3] = -1e30f;
                }
            }

            float mx0 = -1e30f, mx1 = -1e30f;
            #pragma unroll
            for (int nt = 0; nt < 8; nt++){
                mx0 = fmaxf(mx0, fmaxf(s[nt][0], s[nt][1]));
                mx1 = fmaxf(mx1, fmaxf(s[nt][2], s[nt][3]));
            }
            mx0 = fmaxf(mx0, __shfl_xor_sync(0xffffffffu, mx0, 1));
            mx0 = fmaxf(mx0, __shfl_xor_sync(0xffffffffu, mx0, 2));
            mx1 = fmaxf(mx1, __shfl_xor_sync(0xffffffffu, mx1, 1));
            mx1 = fmaxf(mx1, __shfl_xor_sync(0xffffffffu, mx1, 2));
            float mn0 = fmaxf(m0, mx0), mn1 = fmaxf(m1, mx1);
            float al0 = ex2f(m0 - mn0), al1 = ex2f(m1 - mn1);
            m0 = mn0; m1 = mn1;
            #pragma unroll
            for (int nt = 0; nt < 8; nt++){
                sO[nt][0] *= al0; sO[nt][1] *= al0;
                sO[nt][2] *= al1; sO[nt][3] *= al1;
            }
            lac[0] *= al0; lac[1] *= al0; lac[2] *= al1; lac[3] *= al1;

            uint32_t P[8][2];
            #pragma unroll
            for (int nt = 0; nt < 8; nt++){
                P[nt][0] = ex2_f16x2(cvt_f16x2(s[nt][0] - mn0, s[nt][1] - mn0));
                P[nt][1] = ex2_f16x2(cvt_f16x2(s[nt][2] - mn1, s[nt][3] - mn1));
            }

            #pragma unroll
            for (int ks = 0; ks < 4; ks++){
                uint32_t a[4] = {P[2*ks][0], P[2*ks][1], P[2*ks+1][0], P[2*ks+1][1]};
                mma_f16(lac, a, ob);
            }

            uint32_t vb = sb + FS_V + buf*8192;
            #pragma unroll
            for (int ks = 0; ks < 4; ks++){
                uint32_t a[4] = {P[2*ks][0], P[2*ks][1], P[2*ks+1][0], P[2*ks+1][1]};
                #pragma unroll
                for (int dt2 = 0; dt2 < 4; dt2++){
                    int vrow = ks*16 + (lane & 15);
                    int chnk = dt2*2 + (lane >> 4);
                    uint32_t br[4];
                    ldmx4t(br, vb + vrow*128 + ((chnk ^ (vrow & 7)) << 4));
                    uint32_t b0[2] = {br[0], br[1]};
                    uint32_t b1[2] = {br[2], br[3]};
                    mma_f16(sO[dt2*2],     a, b0);
                    mma_f16(sO[dt2*2 + 1], a, b1);
                }
            }
        }

        if (kt + 1 < nkb){
            asm volatile("cp.async.wait_group 0;" ::: "memory");
            __syncthreads();
        }
    }

    float inv0 = 1.0f / lac[0];
    float inv1 = 1.0f / lac[2];
    int tr0 = qt*128 + w*16 + (lane >> 2);
    int tr1 = tr0 + 8;
    #pragma unroll
    for (int dt = 0; dt < 8; dt++){
        int d = dt*8 + (lane & 3)*2;
        size_t i0 = ((size_t)(b * Tq + tr0) * Hq + h) * Dh + d;
        size_t i1 = ((size_t)(b * Tq + tr1) * Hq + h) * Dh + d;
        *(__half2*)(g_o16 + i0) = __halves2half2(
            __float2half_rn(sO[dt][0] * inv0), __float2half_rn(sO[dt][1] * inv0));
        *(__half2*)(g_o16 + i1) = __halves2half2(
            __float2half_rn(sO[dt][2] * inv1), __float2half_rn(sO[dt][3] * inv1));
    }
}

// ---------------------------------------------------------------------------
extern "C" void kernel_launch(void* const* d_in, const int* in_sizes, int n_in,
                              void* d_out, int out_size)
{
    (void)in_sizes; (void)n_in; (void)out_size;
    const float* x     = (const float*)d_in[0];
    const float* cosT  = (const float*)d_in[1];
    const float* sinT  = (const float*)d_in[2];
    const float* w_qkv = (const float*)d_in[3];
    const float* w_out = (const float*)d_in[4];
    float* out = (float*)d_out;

    void *p_x16, *p_wq16, *p_wo16, *p_o16;
    cudaGetSymbolAddress(&p_x16,  g_x16);
    cudaGetSymbolAddress(&p_wq16, g_wq16);
    cudaGetSymbolAddress(&p_wo16, g_wo16);
    cudaGetSymbolAddress(&p_o16,  g_o16);

    cudaFuncSetAttribute(flash_tc, cudaFuncAttributeMaxDynamicSharedMemorySize, FLASH_SMEM);
    cudaFuncSetAttribute(h16_gemm<0>, cudaFuncAttributeMaxDynamicSharedMemorySize, GEMM_SMEM);
    cudaFuncSetAttribute(h16_gemm<1>, cudaFuncAttributeMaxDynamicSharedMemorySize, GEMM_SMEM);

    // 1) fused fp32 -> fp16 converts (one launch)
    cvt_all_kernel<<<(NX4 + NWQ4 + NWO4) / 256, 256>>>(x, w_qkv, w_out);

    // 2) QKV projection with fused RoPE epilogue: Q,K f16 (rotated), V f16
    {
        dim3 grid(3*Cq / 128, MROWS / 128);   // (24, 64)
        h16_gemm<1><<<grid, 256, GEMM_SMEM>>>((const __half*)p_x16, (const __half*)p_wq16,
                                              nullptr, Cq, 3*Cq, cosT, sinT);
    }

    // 3) All-f16 tensor-core causal flash attention -> g_o16 (2 CTAs/SM)
    {
        dim3 grid(Tq / 128, Bq * Hq);
        flash_tc<<<grid, 256, FLASH_SMEM>>>();
    }

    // 4) Output projection
    {
        dim3 grid(Cq / 128, MROWS / 128);     // (8, 64)
        h16_gemm<0><<<grid, 256, GEMM_SMEM>>>((const __half*)p_o16, (const __half*)p_wo16,
                                              out, Cq, Cq, nullptr, nullptr);
    }
}

// round 11
// speedup vs baseline: 1.1345x; 1.0199x over previous
#include <cuda_runtime.h>
#include <cuda_bf16.h>
#include <cuda_fp16.h>
#include <cstdint>

#define Bq 4
#define Tq 2048
#define Cq 1024
#define Hq 16
#define Dh 64
#define MROWS (Bq*Tq)          // 8192
#define NHTD (Bq*Hq*Tq*Dh)     // 8,388,608

// ---------------------------------------------------------------------------
// Device-global scratch
// ---------------------------------------------------------------------------
__device__ __half g_q16[NHTD];           // post-rope, scaled log2e/8, f16 [b,h,t,d]
__device__ __half g_k16[NHTD];           // post-rope, f16 [b,h,t,d]
__device__ __half g_v16[NHTD];           // [b,h,t,d] f16

__device__ __half g_x16[MROWS*Cq];       // x in f16
__device__ __half g_wq16[3*Cq*Cq];       // w_qkv in f16
__device__ __half g_wo16[Cq*Cq];         // w_out in f16
__device__ __half g_o16[MROWS*Cq];       // attention output [b,t,h,d] f16

// ---------------------------------------------------------------------------
// helpers
// ---------------------------------------------------------------------------
__device__ __forceinline__ uint32_t s2u(const void* p){
    uint32_t a;
    asm("{ .reg .u64 t; cvta.to.shared.u64 t, %1; cvt.u32.u64 %0, t; }" : "=r"(a) : "l"(p));
    return a;
}
__device__ __forceinline__ void cp16(uint32_t dst, const void* src){
    asm volatile("cp.async.cg.shared.global [%0], [%1], 16;" :: "r"(dst), "l"(src));
}
__device__ __forceinline__ void ldmx4(uint32_t* r, uint32_t addr){
    asm volatile("ldmatrix.sync.aligned.m8n8.x4.shared.b16 {%0,%1,%2,%3}, [%4];"
                 : "=r"(r[0]), "=r"(r[1]), "=r"(r[2]), "=r"(r[3]) : "r"(addr));
}
__device__ __forceinline__ void ldmx4t(uint32_t* r, uint32_t addr){
    asm volatile("ldmatrix.sync.aligned.m8n8.x4.trans.shared.b16 {%0,%1,%2,%3}, [%4];"
                 : "=r"(r[0]), "=r"(r[1]), "=r"(r[2]), "=r"(r[3]) : "r"(addr));
}
__device__ __forceinline__ void mma_f16(float* c, const uint32_t* a, const uint32_t* b){
    asm volatile(
        "mma.sync.aligned.m16n8k16.row.col.f32.f16.f16.f32 "
        "{%0,%1,%2,%3}, {%4,%5,%6,%7}, {%8,%9}, {%0,%1,%2,%3};"
        : "+f"(c[0]), "+f"(c[1]), "+f"(c[2]), "+f"(c[3])
        : "r"(a[0]), "r"(a[1]), "r"(a[2]), "r"(a[3]), "r"(b[0]), "r"(b[1]));
}
__device__ __forceinline__ uint32_t cvt_f16x2(float lo, float hi){
    uint32_t r;
    asm("cvt.rn.f16x2.f32 %0, %1, %2;" : "=r"(r) : "f"(hi), "f"(lo));
    return r;
}
__device__ __forceinline__ uint32_t ex2_f16x2(uint32_t x){
    uint32_t r;
    asm("ex2.approx.f16x2 %0, %1;" : "=r"(r) : "r"(x));
    return r;
}
__device__ __forceinline__ float ex2f(float x){
    float r;
    asm("ex2.approx.ftz.f32 %0, %1;" : "=f"(r) : "f"(x));
    return r;
}

#define QSC 0.18033688011112042f   // log2(e)/8

// ---------------------------------------------------------------------------
// Fused fp32 -> fp16 convert (x, w_qkv, w_out), 32B per thread.
// ---------------------------------------------------------------------------
#define NX8  (MROWS*Cq/8)        // 1,048,576
#define NWQ8 (3*Cq*Cq/8)         //   393,216
#define NWO8 (Cq*Cq/8)           //   131,072

__global__ void cvt_all_kernel(const float* __restrict__ x,
                               const float* __restrict__ wq,
                               const float* __restrict__ wo)
{
    int i = blockIdx.x * blockDim.x + threadIdx.x;
    const float* src; __half* dst; int off;
    if (i < NX8)              { src = x;  dst = g_x16;  off = i; }
    else if (i < NX8 + NWQ8)  { src = wq; dst = g_wq16; off = i - NX8; }
    else                      { src = wo; dst = g_wo16; off = i - NX8 - NWQ8; }
    float4 v0 = ((const float4*)src)[2*off];
    float4 v1 = ((const float4*)src)[2*off + 1];
    ((__half2*)dst)[4*off]   = __halves2half2(__float2half_rn(v0.x), __float2half_rn(v0.y));
    ((__half2*)dst)[4*off+1] = __halves2half2(__float2half_rn(v0.z), __float2half_rn(v0.w));
    ((__half2*)dst)[4*off+2] = __halves2half2(__float2half_rn(v1.x), __float2half_rn(v1.y));
    ((__half2*)dst)[4*off+3] = __halves2half2(__float2half_rn(v1.z), __float2half_rn(v1.w));
}

// ---------------------------------------------------------------------------
// Single-pass f16 HMMA GEMM (round-10 known-good, byte-identical):
// CTA 128x128, warp tile 64x32 (2x4 warps), K-chunk 64, 3-stage pipeline,
// 2 CTAs/SM. EPI=0: C fp32. EPI=1: V f16 direct; Q/K RoPE-fused f16 out.
// ---------------------------------------------------------------------------
#define ROWB 128
#define OPB (128*ROWB)          // 16384 bytes per operand tile
#define STB (2*OPB)             // 32768 per stage (A+B)
#define GEMM_SMEM (3*STB)       // 98304
#define EPAD 132                // padded f32 row for epilogue staging

template<int EPI>
__global__ __launch_bounds__(256, 2)
void h16_gemm(const __half* __restrict__ A, const __half* __restrict__ B,
              float* __restrict__ C, int K, int Nfull,
              const float* __restrict__ cosT, const float* __restrict__ sinT)
{
    extern __shared__ __align__(1024) char smem[];
    const uint32_t sb = s2u(smem);

    const int tid  = threadIdx.x;
    const int lane = tid & 31;
    const int wid  = tid >> 5;
    const int wM   = wid >> 2;
    const int wN   = wid & 3;
    const int bm = blockIdx.y * 128;
    const int bn = blockIdx.x * 128;
    const int NC = K >> 6;          // 64-wide k-chunks

    float acc[4][4][4];
    #pragma unroll
    for (int i = 0; i < 4; i++)
        #pragma unroll
        for (int j = 0; j < 4; j++)
            #pragma unroll
            for (int q = 0; q < 4; q++) acc[i][j][q] = 0.0f;

    const int rA = ((lane >> 3) & 1) * 8 + (lane & 7);
    const int cA = (lane >> 4) & 1;
    const int rB = lane & 15;
    const int cB = lane >> 4;

    auto prefetch = [&](int c, int st){
        uint32_t base = sb + st * STB;
        int kc = c << 6;
        #pragma unroll
        for (int v = 0; v < 4; v++){
            int idx = tid + v * 256;        // 0..1023
            int row = idx >> 3;             // 0..127
            int ch  = idx & 7;
            uint32_t sw = (uint32_t)(row * ROWB + ((ch ^ (row & 7)) << 4));
            cp16(base + sw,       A + (size_t)(bm + row) * K + kc + ch * 8);
            cp16(base + OPB + sw, B + (size_t)(bn + row) * K + kc + ch * 8);
        }
        asm volatile("cp.async.commit_group;" ::: "memory");
    };

    prefetch(0, 0);
    prefetch(1, 1);
    asm volatile("cp.async.wait_group 1;" ::: "memory");   // stage 0 ready
    __syncthreads();

    for (int c = 0; c < NC; c++){
        int st = c % 3;
        if (c + 2 < NC) prefetch(c + 2, (c + 2) % 3);      // overlaps compute(c)

        uint32_t ab = sb + st * STB;
        uint32_t bb = ab + OPB;
        #pragma unroll
        for (int ks = 0; ks < 4; ks++){
            uint32_t a[4][4];
            #pragma unroll
            for (int i = 0; i < 4; i++){
                int arow = wM*64 + i*16 + rA;
                ldmx4(a[i], ab + arow*ROWB + (((ks*2 + cA) ^ (arow & 7)) << 4));
            }
            uint32_t br[2][4];
            #pragma unroll
            for (int j2 = 0; j2 < 2; j2++){
                int brow = wN*32 + j2*16 + rB;
                ldmx4(br[j2], bb + brow*ROWB + (((ks*2 + cB) ^ (brow & 7)) << 4));
            }
            uint32_t b[4][2];
            #pragma unroll
            for (int j2 = 0; j2 < 2; j2++){
                b[j2*2+0][0] = br[j2][0]; b[j2*2+0][1] = br[j2][2];
                b[j2*2+1][0] = br[j2][1]; b[j2*2+1][1] = br[j2][3];
            }
            #pragma unroll
            for (int i = 0; i < 4; i++)
                #pragma unroll
                for (int j = 0; j < 4; j++)
                    mma_f16(acc[i][j], a[i], b[j]);
        }

        if (c + 1 < NC){
            if (c + 2 < NC){ asm volatile("cp.async.wait_group 1;" ::: "memory"); }
            else           { asm volatile("cp.async.wait_group 0;" ::: "memory"); }
            __syncthreads();
        }
    }

    const int g  = lane >> 2;
    const int tg = lane & 3;
    const int part = bn >> 10;

    if (EPI == 0 || part == 2){
        #pragma unroll
        for (int i = 0; i < 4; i++){
            #pragma unroll
            for (int j = 0; j < 4; j++){
                int col = bn + wN*32 + j*8 + tg*2;
                #pragma unroll
                for (int h2 = 0; h2 < 2; h2++){
                    int m = bm + wM*64 + i*16 + g + h2*8;
                    float2 val = make_float2(acc[i][j][h2*2], acc[i][j][h2*2+1]);
                    if (EPI == 0){
                        *(float2*)(C + (size_t)m * Nfull + col) = val;
                    } else {
                        int hh = (col >> 6) & (Hq - 1);
                        int d0 = col & (Dh - 1);
                        int b  = m >> 11;
                        int t  = m & (Tq - 1);
                        size_t idx = ((size_t)(b*Hq + hh) * Tq + t) * Dh + d0;
                        *(__half2*)(g_v16 + idx) = __halves2half2(
                            __float2half_rn(val.x), __float2half_rn(val.y));
                    }
                }
            }
        }
    } else {
        // Q or K tile: stage to smem, apply RoPE, write f16
        __syncthreads();                      // mainloop smem reads complete
        float* sf = (float*)smem;
        #pragma unroll
        for (int i = 0; i < 4; i++){
            #pragma unroll
            for (int j = 0; j < 4; j++){
                int cl = wN*32 + j*8 + tg*2;
                #pragma unroll
                for (int h2 = 0; h2 < 2; h2++){
                    int ml = wM*64 + i*16 + g + h2*8;
                    *(float2*)&sf[ml*EPAD + cl] =
                        make_float2(acc[i][j][h2*2], acc[i][j][h2*2+1]);
                }
            }
        }
        __syncthreads();

        for (int k = 0; k < 32; k++){
            int p    = tid + k * 256;         // 0..8191
            int row  = p >> 6;                // 0..127
            int pd   = p & 63;
            int hloc = pd >> 5;               // head within tile (0/1)
            int d    = pd & 31;
            int m    = bm + row;
            int t    = m & (Tq - 1);
            int b    = m >> 11;
            float cv = cosT[t * Dh + d];      // cos[t][d] == cos[t][d+32]
            float sv = sinT[t * Dh + d];
            float u1 = sf[row * EPAD + hloc*64 + d];
            float u2 = sf[row * EPAD + hloc*64 + 32 + d];
            float r1 = u1 * cv - u2 * sv;
            float r2 = u2 * cv + u1 * sv;
            int colg = bn + hloc * 64;
            int h    = (colg >> 6) & (Hq - 1);
            size_t idx = ((size_t)(b*Hq + h) * Tq + t) * Dh + d;
            if (part == 0){
                g_q16[idx]      = __float2half_rn(r1 * QSC);
                g_q16[idx + 32] = __float2half_rn(r2 * QSC);
            } else {
                g_k16[idx]      = __float2half_rn(r1);
                g_k16[idx + 32] = __float2half_rn(r2);
            }
        }
    }
}

// ---------------------------------------------------------------------------
// Tensor-core flash attention (causal), all-f16 single-pass.
// 128-wide k-iterations: one prefetch/commit/wait/barrier per TWO 64-col
// sub-blocks (identical arithmetic order to the 64-wide version).
// Smem: Q 16KB + K 2x16KB + V 2x16KB = 80KB; 2 CTAs/SM (160KB <= 228KB).
// ---------------------------------------------------------------------------
#define FS_Q 0            // 128 x 128B
#define FS_K 16384        // buf b: +b*16384, sub-block s: +s*8192
#define FS_V 49152        // buf b: +b*16384, sub-block s: +s*8192
#define FLASH_SMEM 81920

__global__ __launch_bounds__(256, 2)
void flash_tc()
{
    extern __shared__ __align__(1024) char fsm[];
    const uint32_t sb = s2u(fsm);
    const int tid  = threadIdx.x;
    const int lane = tid & 31;
    const int w    = tid >> 5;
    const int qt   = (int)(gridDim.x - 1 - blockIdx.x);
    const int bh   = blockIdx.y;
    const int b    = bh >> 4, h = bh & (Hq - 1);
    const int nit  = qt + 1;          // 128-wide iterations

    // ---- load Q tile (f16), swizzled 128B rows ----
    {
        const __half* q16 = g_q16 + ((size_t)bh * Tq + (size_t)qt * 128) * Dh;
        #pragma unroll
        for (int v = 0; v < 4; v++){
            int idx = tid + v * 256;          // 0..1023
            int row = idx >> 3;               // 0..127
            int c   = idx & 7;
            uint32_t sw = (uint32_t)(row * 128 + ((c ^ (row & 7)) << 4));
            cp16(sb + FS_Q + sw, q16 + (size_t)row * Dh + c * 8);
        }
    }

    // prefetch 128 K rows + 128 V rows (two 64-row sub-blocks)
    auto prefetch = [&](int it, int buf){
        size_t off = ((size_t)bh * Tq + (size_t)it * 128) * Dh;
        const __half* k16 = g_k16 + off;
        const __half* v16 = g_v16 + off;
        #pragma unroll
        for (int v = 0; v < 4; v++){
            int idx = tid + v * 256;          // 0..1023
            int row = idx >> 3;               // 0..127
            int c   = idx & 7;
            // rows 0..63 -> sub-block 0, rows 64..127 -> sub-block 1 (8KB each)
            uint32_t sw = (uint32_t)((row & 63) * 128 + ((c ^ (row & 7)) << 4))
                        + (uint32_t)((row >> 6) * 8192);
            cp16(sb + FS_K + buf*16384 + sw, k16 + (size_t)row * Dh + c * 8);
            cp16(sb + FS_V + buf*16384 + sw, v16 + (size_t)row * Dh + c * 8);
        }
        asm volatile("cp.async.commit_group;" ::: "memory");
    };

    prefetch(0, 0);
    asm volatile("cp.async.wait_group 0;" ::: "memory");
    __syncthreads();

    float sO[8][4];
    #pragma unroll
    for (int i = 0; i < 8; i++)
        #pragma unroll
        for (int q = 0; q < 4; q++) sO[i][q] = 0.0f;
    float lac[4] = {0.f, 0.f, 0.f, 0.f};
    float m0 = -1e30f, m1 = -1e30f;

    const int rA = ((lane >> 3) & 1) * 8 + (lane & 7);
    const int cA = (lane >> 4) & 1;
    const int rB = lane & 15;
    const int cB = lane >> 4;
    const int qrow = w * 16 + rA;
    const uint32_t ONE2 = 0x3C003C00u;
    const uint32_t ob[2] = {ONE2, ONE2};

    for (int it = 0; it < nit; it++){
        int buf = it & 1;
        if (it + 1 < nit) prefetch(it + 1, buf ^ 1);   // overlaps compute(it)

        #pragma unroll
        for (int s = 0; s < 2; s++){
            int kt = 2*it + s;
            bool skip = (kt == 2*qt + 1) && (w < 4);
            if (!skip){
                // ---- S = Q @ K^T, single f16 pass ----
                float sc[8][4];
                #pragma unroll
                for (int i = 0; i < 8; i++)
                    #pragma unroll
                    for (int q = 0; q < 4; q++) sc[i][q] = 0.0f;

                uint32_t kb = sb + FS_K + buf*16384 + s*8192;
                #pragma unroll
                for (int ks = 0; ks < 4; ks++){
                    uint32_t a[4];
                    ldmx4(a, sb + FS_Q + qrow*128 + (((ks*2 + cA) ^ (qrow & 7)) << 4));
                    #pragma unroll
                    for (int j2 = 0; j2 < 4; j2++){
                        int krow = j2*16 + rB;
                        uint32_t br[4];
                        ldmx4(br, kb + krow*128 + (((ks*2 + cB) ^ (krow & 7)) << 4));
                        uint32_t b0[2] = {br[0], br[2]};
                        uint32_t b1[2] = {br[1], br[3]};
                        mma_f16(sc[j2*2],     a, b0);
                        mma_f16(sc[j2*2 + 1], a, b1);
                    }
                }

                // ---- causal mask (diagonal region only) ----
                if (kt >= 2*qt){
                    int co = (kt - 2*qt) * 64;
                    int lr0 = w*16 + (lane >> 2);
                    int lr1 = lr0 + 8;
                    #pragma unroll
                    for (int nt = 0; nt < 8; nt++){
                        int c0 = co + nt*8 + (lane & 3)*2;
                        if (c0     > lr0) sc[nt][0] = -1e30f;
                        if (c0 + 1 > lr0) sc[nt][1] = -1e30f;
                        if (c0     > lr1) sc[nt][2] = -1e30f;
                        if (c0 + 1 > lr1) sc[nt][3] = -1e30f;
                    }
                }

                // ---- online softmax (base-2 domain) ----
                float mx0 = -1e30f, mx1 = -1e30f;
                #pragma unroll
                for (int nt = 0; nt < 8; nt++){
                    mx0 = fmaxf(mx0, fmaxf(sc[nt][0], sc[nt][1]));
                    mx1 = fmaxf(mx1, fmaxf(sc[nt][2], sc[nt][3]));
                }
                mx0 = fmaxf(mx0, __shfl_xor_sync(0xffffffffu, mx0, 1));
                mx0 = fmaxf(mx0, __shfl_xor_sync(0xffffffffu, mx0, 2));
                mx1 = fmaxf(mx1, __shfl_xor_sync(0xffffffffu, mx1, 1));
                mx1 = fmaxf(mx1, __shfl_xor_sync(0xffffffffu, mx1, 2));
                float mn0 = fmaxf(m0, mx0), mn1 = fmaxf(m1, mx1);
                float al0 = ex2f(m0 - mn0), al1 = ex2f(m1 - mn1);
                m0 = mn0; m1 = mn1;
                #pragma unroll
                for (int nt = 0; nt < 8; nt++){
                    sO[nt][0] *= al0; sO[nt][1] *= al0;
                    sO[nt][2] *= al1; sO[nt][3] *= al1;
                }
                lac[0] *= al0; lac[1] *= al0; lac[2] *= al1; lac[3] *= al1;

                // ---- P = 2^(s-m) in f16x2 (PV A-fragment layout) ----
                uint32_t P[8][2];
                #pragma unroll
                for (int nt = 0; nt < 8; nt++){
                    P[nt][0] = ex2_f16x2(cvt_f16x2(sc[nt][0] - mn0, sc[nt][1] - mn0));
                    P[nt][1] = ex2_f16x2(cvt_f16x2(sc[nt][2] - mn1, sc[nt][3] - mn1));
                }

                // ---- row sums: lac += P @ ones ----
                #pragma unroll
                for (int ks = 0; ks < 4; ks++){
                    uint32_t a[4] = {P[2*ks][0], P[2*ks][1], P[2*ks+1][0], P[2*ks+1][1]};
                    mma_f16(lac, a, ob);
                }

                // ---- O += P @ V, single f16 pass ----
                uint32_t vb = sb + FS_V + buf*16384 + s*8192;
                #pragma unroll
                for (int ks = 0; ks < 4; ks++){
                    uint32_t a[4] = {P[2*ks][0], P[2*ks][1], P[2*ks+1][0], P[2*ks+1][1]};
                    #pragma unroll
                    for (int dt2 = 0; dt2 < 4; dt2++){
                        int vrow = ks*16 + (lane & 15);
                        int chnk = dt2*2 + (lane >> 4);
                        uint32_t br[4];
                        ldmx4t(br, vb + vrow*128 + ((chnk ^ (vrow & 7)) << 4));
                        uint32_t b0[2] = {br[0], br[1]};
                        uint32_t b1[2] = {br[2], br[3]};
                        mma_f16(sO[dt2*2],     a, b0);
                        mma_f16(sO[dt2*2 + 1], a, b1);
                    }
                }
            }
        }

        if (it + 1 < nit){
            asm volatile("cp.async.wait_group 0;" ::: "memory");
            __syncthreads();
        }
    }

    // ---- epilogue: normalize, write f16 at [b,t,h,d] ----
    float inv0 = 1.0f / lac[0];
    float inv1 = 1.0f / lac[2];
    int tr0 = qt*128 + w*16 + (lane >> 2);
    int tr1 = tr0 + 8;
    #pragma unroll
    for (int dt = 0; dt < 8; dt++){
        int d = dt*8 + (lane & 3)*2;
        size_t i0 = ((size_t)(b * Tq + tr0) * Hq + h) * Dh + d;
        size_t i1 = ((size_t)(b * Tq + tr1) * Hq + h) * Dh + d;
        *(__half2*)(g_o16 + i0) = __halves2half2(
            __float2half_rn(sO[dt][0] * inv0), __float2half_rn(sO[dt][1] * inv0));
        *(__half2*)(g_o16 + i1) = __halves2half2(
            __float2half_rn(sO[dt][2] * inv1), __float2half_rn(sO[dt][3] * inv1));
    }
}

// ---------------------------------------------------------------------------
extern "C" void kernel_launch(void* const* d_in, const int* in_sizes, int n_in,
                              void* d_out, int out_size)
{
    (void)in_sizes; (void)n_in; (void)out_size;
    const float* x     = (const float*)d_in[0];
    const float* cosT  = (const float*)d_in[1];
    const float* sinT  = (const float*)d_in[2];
    const float* w_qkv = (const float*)d_in[3];
    const float* w_out = (const float*)d_in[4];
    float* out = (float*)d_out;

    void *p_x16, *p_wq16, *p_wo16, *p_o16;
    cudaGetSymbolAddress(&p_x16,  g_x16);
    cudaGetSymbolAddress(&p_wq16, g_wq16);
    cudaGetSymbolAddress(&p_wo16, g_wo16);
    cudaGetSymbolAddress(&p_o16,  g_o16);

    cudaFuncSetAttribute(flash_tc, cudaFuncAttributeMaxDynamicSharedMemorySize, FLASH_SMEM);
    cudaFuncSetAttribute(h16_gemm<0>, cudaFuncAttributeMaxDynamicSharedMemorySize, GEMM_SMEM);
    cudaFuncSetAttribute(h16_gemm<1>, cudaFuncAttributeMaxDynamicSharedMemorySize, GEMM_SMEM);

    // 1) fused fp32 -> fp16 converts (one launch, 32B/thread)
    cvt_all_kernel<<<(NX8 + NWQ8 + NWO8) / 256, 256>>>(x, w_qkv, w_out);

    // 2) QKV projection with fused RoPE epilogue: Q,K f16 (rotated), V f16
    {
        dim3 grid(3*Cq / 128, MROWS / 128);   // (24, 64)
        h16_gemm<1><<<grid, 256, GEMM_SMEM>>>((const __half*)p_x16, (const __half*)p_wq16,
                                              nullptr, Cq, 3*Cq, cosT, sinT);
    }

    // 3) All-f16 tensor-core causal flash attention -> g_o16 (2 CTAs/SM)
    {
        dim3 grid(Tq / 128, Bq * Hq);
        flash_tc<<<grid, 256, FLASH_SMEM>>>();
    }

    // 4) Output projection
    {
        dim3 grid(Cq / 128, MROWS / 128);     // (8, 64)
        h16_gemm<0><<<grid, 256, GEMM_SMEM>>>((const __half*)p_o16, (const __half*)p_wo16,
                                              out, Cq, Cq, nullptr, nullptr);
    }
}